// round 1
// baseline (speedup 1.0000x reference)
#include <cuda_runtime.h>
#include <cuda_bf16.h>
#include <cstdint>

// Problem constants
#define Bsz   256
#define Tsz   250
#define DIN   700
#define Hd    128
#define DOUT  20

// Scratch: h1_all[t][b][h]  (32.77 MB)
__device__ float g_h1[Tsz * Bsz * Hd];

// ---------------------------------------------------------------------------
// Kernel 1: h1_all = x @ W1 + b1
// x: [B, T, DIN] row-major  ->  row m = b*T + t
// out: g_h1[t*B*H + b*H + n]
// 128x128x32 tile, 256 threads, 8x8 microtile
// ---------------------------------------------------------------------------
__global__ void __launch_bounds__(256) gemm1_kernel(
    const float* __restrict__ x,
    const float* __restrict__ W1,
    const float* __restrict__ b1)
{
    __shared__ float As[32][132];   // transposed A tile, padded for fp4 align + banks
    __shared__ float Bs[32][128];

    const int tid = threadIdx.x;
    const int m0  = blockIdx.x * 128;
    const int tx  = tid & 15;       // 16 cols of threads
    const int ty  = tid >> 4;       // 16 rows of threads

    float acc[8][8];
    #pragma unroll
    for (int i = 0; i < 8; i++)
        #pragma unroll
        for (int j = 0; j < 8; j++) acc[i][j] = 0.f;

    for (int kt = 0; kt < DIN; kt += 32) {
        // Load A tile: 128 rows x 32 k  (transposed into As[kk][m])
        #pragma unroll
        for (int i = 0; i < 16; i++) {
            int idx = tid + i * 256;
            int kk = idx & 31;
            int ml = idx >> 5;
            int k  = kt + kk;
            As[kk][ml] = (k < DIN) ? x[(size_t)(m0 + ml) * DIN + k] : 0.f;
        }
        // Load B tile: 32 k x 128 n
        #pragma unroll
        for (int i = 0; i < 16; i++) {
            int idx = tid + i * 256;
            int n  = idx & 127;
            int kk = idx >> 7;
            int k  = kt + kk;
            Bs[kk][n] = (k < DIN) ? W1[k * Hd + n] : 0.f;
        }
        __syncthreads();

        #pragma unroll
        for (int kk = 0; kk < 32; kk++) {
            float a[8], b[8];
            *(float4*)&a[0] = *(const float4*)&As[kk][ty * 8];
            *(float4*)&a[4] = *(const float4*)&As[kk][ty * 8 + 4];
            *(float4*)&b[0] = *(const float4*)&Bs[kk][tx * 8];
            *(float4*)&b[4] = *(const float4*)&Bs[kk][tx * 8 + 4];
            #pragma unroll
            for (int i = 0; i < 8; i++)
                #pragma unroll
                for (int j = 0; j < 8; j++)
                    acc[i][j] += a[i] * b[j];
        }
        __syncthreads();
    }

    // Store with bias, scattered to [t][b][n]
    float bias[8];
    #pragma unroll
    for (int j = 0; j < 8; j++) bias[j] = b1[tx * 8 + j];

    #pragma unroll
    for (int i = 0; i < 8; i++) {
        int m = m0 + ty * 8 + i;
        int b = m / Tsz;
        int t = m - b * Tsz;
        float* o = g_h1 + (size_t)t * (Bsz * Hd) + b * Hd + tx * 8;
        #pragma unroll
        for (int j = 0; j < 8; j++) o[j] = acc[i][j] + bias[j];
    }
}

// ---------------------------------------------------------------------------
// Kernel 2: persistent recurrent LIF loop.
// 128 CTAs x 256 threads; each half-CTA (128 threads) owns one batch sample.
// All weights resident in SMEM. Spike-sparse row-sum GEMVs with deterministic
// ballot-compacted active lists.
// ---------------------------------------------------------------------------
#define SM_W0   0                      // rcW1  16384 f
#define SM_W1   16384                  // W2    16384 f
#define SM_W2   32768                  // rcW2  16384 f
#define SM_W3   49152                  // W3     2560 f
#define SM_RCB1 51712                  // rcb1    128 f
#define SM_B2C  51840                  // b2+rcb2 128 f
#define SM_L1   51968                  // int l1[2][128]
#define SM_L2   52224                  // int l2[2][128]
#define SM_WM   52480                  // unsigned wm[8]
#define SM_FLOATS 52488
#define SM_BYTES  (SM_FLOATS * 4)      // 209,952 B

__global__ void __launch_bounds__(256, 1) rec_kernel(
    const float* __restrict__ rcW1, const float* __restrict__ rcb1,
    const float* __restrict__ W2,   const float* __restrict__ b2,
    const float* __restrict__ rcW2, const float* __restrict__ rcb2,
    const float* __restrict__ W3,   const float* __restrict__ b3,
    float* __restrict__ out)
{
    extern __shared__ float sm[];
    float* sW0   = sm + SM_W0;
    float* sW1   = sm + SM_W1;
    float* sW2   = sm + SM_W2;
    float* sW3   = sm + SM_W3;
    float* srcb1 = sm + SM_RCB1;
    float* sb2c  = sm + SM_B2C;
    int*   sl1   = (int*)(sm + SM_L1);
    int*   sl2   = (int*)(sm + SM_L2);
    unsigned* swm = (unsigned*)(sm + SM_WM);

    const int tid = threadIdx.x;

    // Load weights into SMEM (coalesced)
    for (int i = tid; i < Hd * Hd; i += 256) {
        sW0[i] = rcW1[i];
        sW1[i] = W2[i];
        sW2[i] = rcW2[i];
    }
    for (int i = tid; i < Hd * DOUT; i += 256) sW3[i] = W3[i];
    if (tid < Hd) {
        srcb1[tid] = rcb1[tid];
        sb2c[tid]  = b2[tid] + rcb2[tid];
    }
    __syncthreads();

    const int hb   = tid >> 7;           // half index (sample within CTA)
    const int j    = tid & 127;          // neuron index
    const int b    = blockIdx.x * 2 + hb;
    const int lane = tid & 31;
    const int w    = (tid >> 5) & 3;     // warp within half

    int*      l1 = sl1 + hb * 128;
    int*      l2 = sl2 + hb * 128;
    unsigned* wm = swm + hb * 4;

    float v1 = 0.f, v2 = 0.f, acc = 0.f;
    int n1 = 0, n2 = 0;

    const float* h1p = g_h1 + b * Hd + j;

    for (int t = 0; t < Tsz; t++) {
        // ---- u1 = h1 + rcb1 + sum of active rcW1 rows ----
        float u = h1p[t * (Bsz * Hd)] + srcb1[j];
        {
            float a0 = 0.f, a1 = 0.f, a2 = 0.f, a3 = 0.f;
            int k = 0;
            for (; k + 4 <= n1; k += 4) {
                int i0 = l1[k], i1 = l1[k+1], i2 = l1[k+2], i3 = l1[k+3];
                a0 += sW0[i0 * Hd + j];
                a1 += sW0[i1 * Hd + j];
                a2 += sW0[i2 * Hd + j];
                a3 += sW0[i3 * Hd + j];
            }
            for (; k < n1; k++) a0 += sW0[l1[k] * Hd + j];
            u += (a0 + a1) + (a2 + a3);
        }
        // LIF 1:  v += (u - v)/2 ; spike at v >= 1 ; hard reset
        v1 += (u - v1) * 0.5f;
        bool s1 = (v1 >= 1.0f);
        if (s1) v1 = 0.f;

        __syncthreads();                       // all reads of old l1 done
        unsigned m = __ballot_sync(0xffffffffu, s1);
        if (lane == 0) wm[w] = m;
        __syncthreads();
        {
            unsigned q0 = wm[0], q1 = wm[1], q2 = wm[2], q3 = wm[3];
            int base = 0;
            if (w > 0) base += __popc(q0);
            if (w > 1) base += __popc(q1);
            if (w > 2) base += __popc(q2);
            if (s1) l1[base + __popc(m & ((1u << lane) - 1u))] = j;
            n1 = __popc(q0) + __popc(q1) + __popc(q2) + __popc(q3);
        }
        __syncthreads();                       // new l1 visible

        // ---- u2 = b2 + rcb2 + s1@W2 + y2_old@rcW2 ----
        float u2 = sb2c[j];
        {
            float a0 = 0.f, a1 = 0.f, a2 = 0.f, a3 = 0.f;
            int k = 0;
            for (; k + 4 <= n1; k += 4) {
                int i0 = l1[k], i1 = l1[k+1], i2 = l1[k+2], i3 = l1[k+3];
                a0 += sW1[i0 * Hd + j];
                a1 += sW1[i1 * Hd + j];
                a2 += sW1[i2 * Hd + j];
                a3 += sW1[i3 * Hd + j];
            }
            for (; k < n1; k++) a0 += sW1[l1[k] * Hd + j];
            int k2 = 0;
            for (; k2 + 4 <= n2; k2 += 4) {
                int i0 = l2[k2], i1 = l2[k2+1], i2 = l2[k2+2], i3 = l2[k2+3];
                a0 += sW2[i0 * Hd + j];
                a1 += sW2[i1 * Hd + j];
                a2 += sW2[i2 * Hd + j];
                a3 += sW2[i3 * Hd + j];
            }
            for (; k2 < n2; k2++) a0 += sW2[l2[k2] * Hd + j];
            u2 += (a0 + a1) + (a2 + a3);
        }
        // LIF 2
        v2 += (u2 - v2) * 0.5f;
        bool s2 = (v2 >= 1.0f);
        if (s2) v2 = 0.f;

        __syncthreads();                       // all reads of old l2 done
        m = __ballot_sync(0xffffffffu, s2);
        if (lane == 0) wm[w] = m;
        __syncthreads();
        {
            unsigned q0 = wm[0], q1 = wm[1], q2 = wm[2], q3 = wm[3];
            int base = 0;
            if (w > 0) base += __popc(q0);
            if (w > 1) base += __popc(q1);
            if (w > 2) base += __popc(q2);
            if (s2) l2[base + __popc(m & ((1u << lane) - 1u))] = j;
            n2 = __popc(q0) + __popc(q1) + __popc(q2) + __popc(q3);
        }
        __syncthreads();                       // new l2 visible

        // ---- readout: acc += s2 @ W3 ----
        if (j < DOUT) {
            float a = 0.f;
            for (int k = 0; k < n2; k++) a += sW3[l2[k] * DOUT + j];
            acc += a;
        }
    }

    if (j < DOUT)
        out[b * DOUT + j] = acc + (float)Tsz * b3[j];
}

// ---------------------------------------------------------------------------
// Launch
// Inputs (metadata order): x, W1, b1, rcW1, rcb1, W2, b2, rcW2, rcb2, W3, b3
// ---------------------------------------------------------------------------
extern "C" void kernel_launch(void* const* d_in, const int* in_sizes, int n_in,
                              void* d_out, int out_size)
{
    const float* x    = (const float*)d_in[0];
    const float* W1   = (const float*)d_in[1];
    const float* b1   = (const float*)d_in[2];
    const float* rcW1 = (const float*)d_in[3];
    const float* rcb1 = (const float*)d_in[4];
    const float* W2   = (const float*)d_in[5];
    const float* b2   = (const float*)d_in[6];
    const float* rcW2 = (const float*)d_in[7];
    const float* rcb2 = (const float*)d_in[8];
    const float* W3   = (const float*)d_in[9];
    const float* b3   = (const float*)d_in[10];
    float* out = (float*)d_out;

    cudaFuncSetAttribute(rec_kernel,
                         cudaFuncAttributeMaxDynamicSharedMemorySize, SM_BYTES);

    // 1) h1_all = x @ W1 + b1   (M = B*T = 64000 -> 500 tiles of 128)
    gemm1_kernel<<<(Bsz * Tsz) / 128, 256>>>(x, W1, b1);

    // 2) recurrent LIF loop, 2 samples per CTA
    rec_kernel<<<Bsz / 2, 256, SM_BYTES>>>(rcW1, rcb1, W2, b2,
                                           rcW2, rcb2, W3, b3, out);
}

// round 2
// speedup vs baseline: 1.2827x; 1.2827x over previous
#include <cuda_runtime.h>
#include <cuda_bf16.h>
#include <cstdint>

// Problem constants
#define Bsz   256
#define Tsz   250
#define DIN   700
#define Hd    128
#define DOUT  20

// Scratch: h1_all[t][b][h]  (32.77 MB)
__device__ float g_h1[Tsz * Bsz * Hd];

typedef unsigned long long u64;

// ---- packed f32x2 helpers (sm_100+) --------------------------------------
__device__ __forceinline__ u64 pack2(float x, float y) {
    u64 r; asm("mov.b64 %0, {%1, %2};" : "=l"(r) : "f"(x), "f"(y)); return r;
}
__device__ __forceinline__ void unpack2(u64 p, float& x, float& y) {
    asm("mov.b64 {%0, %1}, %2;" : "=f"(x), "=f"(y) : "l"(p));
}
__device__ __forceinline__ u64 fma2(u64 a, u64 b, u64 c) {
    u64 d; asm("fma.rn.f32x2 %0, %1, %2, %3;" : "=l"(d) : "l"(a), "l"(b), "l"(c));
    return d;
}

// ---------------------------------------------------------------------------
// Kernel 1: h1_all = x @ W1 + b1   (fp32, packed f32x2 FMA microkernel)
// x: [B, T, DIN] row-major; out: g_h1[t*B*H + b*H + n]
// 128x128x32 tile, 256 threads, 8x8 microtile (as 8x4 f32x2 pairs)
// ---------------------------------------------------------------------------
__global__ void __launch_bounds__(256) gemm1_kernel(
    const float* __restrict__ x,
    const float* __restrict__ W1,
    const float* __restrict__ b1)
{
    __shared__ float As[32][132];   // transposed A tile (pad keeps 16B align)
    __shared__ float Bs[32][128];

    const int tid = threadIdx.x;
    const int m0  = blockIdx.x * 128;
    const int tx  = tid & 15;       // 16 cols of threads
    const int ty  = tid >> 4;       // 16 rows of threads

    u64 accp[8][4];
    #pragma unroll
    for (int i = 0; i < 8; i++)
        #pragma unroll
        for (int j = 0; j < 4; j++) accp[i][j] = 0ull;   // {0.f,0.f}

    for (int kt = 0; kt < DIN; kt += 32) {
        #pragma unroll
        for (int i = 0; i < 16; i++) {
            int idx = tid + i * 256;
            int kk = idx & 31;
            int ml = idx >> 5;
            int k  = kt + kk;
            As[kk][ml] = (k < DIN) ? x[(size_t)(m0 + ml) * DIN + k] : 0.f;
        }
        #pragma unroll
        for (int i = 0; i < 16; i++) {
            int idx = tid + i * 256;
            int n  = idx & 127;
            int kk = idx >> 7;
            int k  = kt + kk;
            Bs[kk][n] = (k < DIN) ? W1[k * Hd + n] : 0.f;
        }
        __syncthreads();

        #pragma unroll
        for (int kk = 0; kk < 32; kk++) {
            float a[8];
            *(float4*)&a[0] = *(const float4*)&As[kk][ty * 8];
            *(float4*)&a[4] = *(const float4*)&As[kk][ty * 8 + 4];
            ulonglong2 q0 = *(const ulonglong2*)&Bs[kk][tx * 8];
            ulonglong2 q1 = *(const ulonglong2*)&Bs[kk][tx * 8 + 4];
            #pragma unroll
            for (int i = 0; i < 8; i++) {
                u64 ai = pack2(a[i], a[i]);
                accp[i][0] = fma2(ai, q0.x, accp[i][0]);
                accp[i][1] = fma2(ai, q0.y, accp[i][1]);
                accp[i][2] = fma2(ai, q1.x, accp[i][2]);
                accp[i][3] = fma2(ai, q1.y, accp[i][3]);
            }
        }
        __syncthreads();
    }

    float bias[8];
    #pragma unroll
    for (int j = 0; j < 8; j++) bias[j] = b1[tx * 8 + j];

    #pragma unroll
    for (int i = 0; i < 8; i++) {
        int m = m0 + ty * 8 + i;
        int b = m / Tsz;
        int t = m - b * Tsz;
        float* o = g_h1 + (size_t)t * (Bsz * Hd) + b * Hd + tx * 8;
        #pragma unroll
        for (int j4 = 0; j4 < 4; j4++) {
            float lo, hi;
            unpack2(accp[i][j4], lo, hi);
            o[j4 * 2 + 0] = lo + bias[j4 * 2 + 0];
            o[j4 * 2 + 1] = hi + bias[j4 * 2 + 1];
        }
    }
}

// ---------------------------------------------------------------------------
// Kernel 2: persistent recurrent LIF loop.
// 128 CTAs x 256 threads; each half-CTA (128 threads) owns one batch sample.
// Spike state kept as 4x32-bit ballot masks in REGISTERS; one smem broadcast
// (4 words) + ONE named 128-thread barrier per LIF phase => 2 barriers/step.
// ---------------------------------------------------------------------------
#define SM_W0   0                       // rcW1   16384 f
#define SM_W1   16384                   // W2     16384 f
#define SM_W2   32768                   // rcW2   16384 f
#define SM_W3   49152                   // W3      2560 f  [i*20+j]
#define SM_RCB1 51712                   // rcb1     128 f
#define SM_B2C  51840                   // b2+rcb2  128 f
#define SM_WM1  51968                   // unsigned [2][4]
#define SM_WM2  51976                   // unsigned [2][4]
#define SM_FLOATS 51984
#define SM_BYTES  (SM_FLOATS * 4)       // 207,936 B

__global__ void __launch_bounds__(256, 1) rec_kernel(
    const float* __restrict__ rcW1, const float* __restrict__ rcb1,
    const float* __restrict__ W2,   const float* __restrict__ b2,
    const float* __restrict__ rcW2, const float* __restrict__ rcb2,
    const float* __restrict__ W3,   const float* __restrict__ b3,
    float* __restrict__ out)
{
    extern __shared__ float sm[];
    float* sW0   = sm + SM_W0;
    float* sW1   = sm + SM_W1;
    float* sW2   = sm + SM_W2;
    float* sW3   = sm + SM_W3;
    float* srcb1 = sm + SM_RCB1;
    float* sb2c  = sm + SM_B2C;
    unsigned* swm1 = (unsigned*)(sm + SM_WM1);
    unsigned* swm2 = (unsigned*)(sm + SM_WM2);

    const int tid = threadIdx.x;

    // Load weights into SMEM (coalesced, vectorized)
    {
        const float4* a = (const float4*)rcW1;
        const float4* c = (const float4*)W2;
        const float4* d = (const float4*)rcW2;
        float4* o0 = (float4*)sW0; float4* o1 = (float4*)sW1; float4* o2 = (float4*)sW2;
        for (int i = tid; i < (Hd * Hd) / 4; i += 256) {
            o0[i] = a[i]; o1[i] = c[i]; o2[i] = d[i];
        }
    }
    for (int i = tid; i < Hd * DOUT; i += 256) sW3[i] = W3[i];
    if (tid < Hd) {
        srcb1[tid] = rcb1[tid];
        sb2c[tid]  = b2[tid] + rcb2[tid];
    }
    __syncthreads();

    const int hb   = tid >> 7;           // half index (sample within CTA)
    const int j    = tid & 127;          // neuron index
    const int b    = blockIdx.x * 2 + hb;
    const int lane = tid & 31;
    const int w    = (tid >> 5) & 3;     // warp within half
    const int barid = 1 + hb;            // named barrier per half

    unsigned* wm1 = swm1 + hb * 4;
    unsigned* wm2 = swm2 + hb * 4;

    float v1 = 0.f, v2 = 0.f, acc = 0.f;
    unsigned m1[4] = {0u, 0u, 0u, 0u};   // y1 spike masks (prev step)
    unsigned m2[4] = {0u, 0u, 0u, 0u};   // y2 spike masks (prev step)

    const float* h1p = g_h1 + b * Hd + j;
    float h1v = h1p[0];

    for (int t = 0; t < Tsz; t++) {
        // Prefetch next step's h1 (hides DRAM latency under compute)
        float h1n = (t + 1 < Tsz) ? h1p[(size_t)(t + 1) * (Bsz * Hd)] : 0.f;

        // ---- u1 = h1 + rcb1 + y1_old @ rcW1 (mask-gathered row sums) ----
        float u = h1v + srcb1[j];
        #pragma unroll
        for (int q = 0; q < 4; q++) {
            unsigned mm = m1[q];
            const float* wp = sW0 + q * 32 * Hd + j;
            while (mm) {
                int i = __ffs(mm) - 1; mm &= mm - 1u;
                u += wp[i * Hd];
            }
        }
        // LIF 1
        v1 += (u - v1) * 0.5f;
        bool s1 = (v1 >= 1.0f);
        if (s1) v1 = 0.f;

        unsigned bal = __ballot_sync(0xffffffffu, s1);
        if (lane == 0) wm1[w] = bal;
        asm volatile("bar.sync %0, 128;" :: "r"(barid) : "memory");
        m1[0] = wm1[0]; m1[1] = wm1[1]; m1[2] = wm1[2]; m1[3] = wm1[3];

        // ---- u2 = b2 + rcb2 + y1_new @ W2 + y2_old @ rcW2 ----
        float u2 = sb2c[j];
        #pragma unroll
        for (int q = 0; q < 4; q++) {
            unsigned mm = m1[q];
            const float* wp = sW1 + q * 32 * Hd + j;
            while (mm) {
                int i = __ffs(mm) - 1; mm &= mm - 1u;
                u2 += wp[i * Hd];
            }
        }
        #pragma unroll
        for (int q = 0; q < 4; q++) {
            unsigned mm = m2[q];
            const float* wp = sW2 + q * 32 * Hd + j;
            while (mm) {
                int i = __ffs(mm) - 1; mm &= mm - 1u;
                u2 += wp[i * Hd];
            }
        }
        // LIF 2
        v2 += (u2 - v2) * 0.5f;
        bool s2 = (v2 >= 1.0f);
        if (s2) v2 = 0.f;

        bal = __ballot_sync(0xffffffffu, s2);
        if (lane == 0) wm2[w] = bal;
        asm volatile("bar.sync %0, 128;" :: "r"(barid) : "memory");
        m2[0] = wm2[0]; m2[1] = wm2[1]; m2[2] = wm2[2]; m2[3] = wm2[3];

        // ---- readout: acc += y2_new @ W3 (only 20 lanes work; others run
        //      ahead into next step's phase-1 compute) ----
        if (j < DOUT) {
            float a = 0.f;
            #pragma unroll
            for (int q = 0; q < 4; q++) {
                unsigned mm = m2[q];
                const float* wp = sW3 + q * 32 * DOUT + j;
                while (mm) {
                    int i = __ffs(mm) - 1; mm &= mm - 1u;
                    a += wp[i * DOUT];
                }
            }
            acc += a;
        }
        h1v = h1n;
    }

    if (j < DOUT)
        out[b * DOUT + j] = acc + (float)Tsz * b3[j];
}

// ---------------------------------------------------------------------------
// Launch
// Inputs (metadata order): x, W1, b1, rcW1, rcb1, W2, b2, rcW2, rcb2, W3, b3
// ---------------------------------------------------------------------------
extern "C" void kernel_launch(void* const* d_in, const int* in_sizes, int n_in,
                              void* d_out, int out_size)
{
    const float* x    = (const float*)d_in[0];
    const float* W1   = (const float*)d_in[1];
    const float* b1   = (const float*)d_in[2];
    const float* rcW1 = (const float*)d_in[3];
    const float* rcb1 = (const float*)d_in[4];
    const float* W2   = (const float*)d_in[5];
    const float* b2   = (const float*)d_in[6];
    const float* rcW2 = (const float*)d_in[7];
    const float* rcb2 = (const float*)d_in[8];
    const float* W3   = (const float*)d_in[9];
    const float* b3   = (const float*)d_in[10];
    float* out = (float*)d_out;

    cudaFuncSetAttribute(rec_kernel,
                         cudaFuncAttributeMaxDynamicSharedMemorySize, SM_BYTES);

    // 1) h1_all = x @ W1 + b1
    gemm1_kernel<<<(Bsz * Tsz) / 128, 256>>>(x, W1, b1);

    // 2) recurrent LIF loop, 2 samples per CTA, per-sample named barriers
    rec_kernel<<<Bsz / 2, 256, SM_BYTES>>>(rcW1, rcb1, W2, b2,
                                           rcW2, rcb2, W3, b3, out);
}

// round 4
// speedup vs baseline: 1.5395x; 1.2002x over previous
#include <cuda_runtime.h>
#include <cuda_bf16.h>
#include <cstdint>

// Problem constants
#define Bsz   256
#define Tsz   250
#define DIN   700
#define Hd    128
#define DOUT  20
#define KT    64            // k-tile
#define NKT   11            // 704 / 64

// Scratch
__device__ float g_h1[Tsz * Bsz * Hd];                 // h1_all[t][b][h]
__device__ __nv_bfloat16 g_Bh[NKT * 128 * KT];          // W1^T splits [kt][n][kk]
__device__ __nv_bfloat16 g_Bm[NKT * 128 * KT];
__device__ __nv_bfloat16 g_Bl[NKT * 128 * KT];

// ---- exact truncation split: a = h + m + l, each bf16-exact ---------------
__device__ __forceinline__ void bsplit(float a, float& h, float& m, float& l) {
    h = __uint_as_float(__float_as_uint(a) & 0xFFFF0000u);
    float r = a - h;                                    // exact
    m = __uint_as_float(__float_as_uint(r) & 0xFFFF0000u);
    l = r - m;                                          // exact, <=8 bits
}
// pack two bf16 (top halves of fp32 bit patterns) into one u32
__device__ __forceinline__ uint32_t hpack(float a, float b) {
    return __byte_perm(__float_as_uint(a), __float_as_uint(b), 0x7632);
}

// ---------------------------------------------------------------------------
// Prep: split W1 -> g_B{h,m,l}[kt][n][kk], zero pad k>=700
// ---------------------------------------------------------------------------
__global__ void prep_kernel(const float* __restrict__ W1)
{
    int idx = blockIdx.x * blockDim.x + threadIdx.x;    // 0 .. 11*128*64-1
    if (idx >= NKT * 128 * KT) return;
    int kt = idx / (128 * KT);
    int r  = idx - kt * (128 * KT);
    int n  = r >> 6;
    int kk = r & 63;
    int k  = kt * KT + kk;
    float w = (k < DIN) ? W1[k * Hd + n] : 0.f;
    float h, m, l;
    bsplit(w, h, m, l);
    g_Bh[idx] = __float2bfloat16(h);
    g_Bm[idx] = __float2bfloat16(m);
    g_Bl[idx] = __float2bfloat16(l);
}

// ---------------------------------------------------------------------------
// mma.sync helpers (base sm_103 ISA — no tcgen05)
// ---------------------------------------------------------------------------
__device__ __forceinline__ void mma_bf16(float* d, const uint32_t* a,
                                         const uint32_t* b) {
    asm volatile(
        "mma.sync.aligned.m16n8k16.row.col.f32.bf16.bf16.f32 "
        "{%0,%1,%2,%3}, {%4,%5,%6,%7}, {%8,%9}, {%0,%1,%2,%3};"
        : "+f"(d[0]), "+f"(d[1]), "+f"(d[2]), "+f"(d[3])
        : "r"(a[0]), "r"(a[1]), "r"(a[2]), "r"(a[3]), "r"(b[0]), "r"(b[1]));
}
__device__ __forceinline__ void ldsm4(uint32_t* r, uint32_t addr) {
    asm volatile("ldmatrix.sync.aligned.m8n8.x4.shared.b16 {%0,%1,%2,%3}, [%4];"
                 : "=r"(r[0]), "=r"(r[1]), "=r"(r[2]), "=r"(r[3]) : "r"(addr));
}
__device__ __forceinline__ uint32_t smem_u32(const void* p) {
    uint32_t a;
    asm("{ .reg .u64 t; cvta.to.shared.u64 t, %1; cvt.u32.u64 %0, t; }"
        : "=r"(a) : "l"(p));
    return a;
}

// smem byte offsets (rows are 64 bf16 = 128B, XOR-16 swizzle on (row&7))
#define GS_AH   0
#define GS_AM   16384
#define GS_AL   32768
#define GS_BH   49152
#define GS_BM   65536
#define GS_BL   81920
#define GS_BIAS 98304
#define GS_BYTES (GS_BIAS + 512)

// ---------------------------------------------------------------------------
// Kernel 1: h1_all = x @ W1 + b1 via bf16x3 (6-product, fp32-accurate) HMMA
// CTA: 128x128 tile. 8 warps: mw = wid&1 (2 x 64 rows), nw = wid>>1 (4 x 32 cols)
// ---------------------------------------------------------------------------
__global__ void __launch_bounds__(256, 1) gemm1_kernel(
    const float* __restrict__ x,
    const float* __restrict__ b1)
{
    extern __shared__ char smg[];
    const uint32_t sbase = smem_u32(smg);
    const int tid  = threadIdx.x;
    const int wid  = tid >> 5;
    const int lane = tid & 31;
    const int mw   = wid & 1;
    const int nw   = wid >> 1;
    const int m0   = blockIdx.x * 128;

    if (tid < 128) ((float*)(smg + GS_BIAS))[tid] = b1[tid];

    float acc[4][4][4];
    #pragma unroll
    for (int i = 0; i < 4; i++)
        #pragma unroll
        for (int j = 0; j < 4; j++)
            #pragma unroll
            for (int c = 0; c < 4; c++) acc[i][j][c] = 0.f;

    // A loader mapping: one row per 2 threads
    const int arow = tid >> 1;           // 0..127
    const int akh  = tid & 1;            // which 32-float half of the row
    const float* xrow = x + (size_t)(m0 + arow) * DIN;
    const uint32_t aswz = (uint32_t)((arow & 7) << 4);
    const uint32_t abase = (uint32_t)(arow * 128);

    // ldmatrix per-lane address components
    const int ra = (lane & 7) + ((lane >> 3) & 1) * 8;   // A row offset
    const int ka = (lane >> 4) * 8;                      // A k offset
    const int rb = (lane & 7) + (lane >> 4) * 8;         // B n-row offset
    const int kbl = ((lane >> 3) & 1) * 8;               // B k offset
    const uint32_t lswz = (uint32_t)((lane & 7) << 4);

    for (int kt = 0; kt < NKT; kt++) {
        // ---- load + split A tile: 128 rows x 64 k (8 floats/thread/iter) ----
        #pragma unroll
        for (int i = 0; i < 4; i++) {
            int kl = akh * 32 + i * 8;
            int gk = kt * KT + kl;
            float4 v0 = (gk <= DIN - 4) ? *(const float4*)(xrow + gk)
                                        : make_float4(0.f, 0.f, 0.f, 0.f);
            float4 v1 = (gk + 4 <= DIN - 4) ? *(const float4*)(xrow + gk + 4)
                                            : make_float4(0.f, 0.f, 0.f, 0.f);
            float h[8], m[8], l[8];
            bsplit(v0.x, h[0], m[0], l[0]); bsplit(v0.y, h[1], m[1], l[1]);
            bsplit(v0.z, h[2], m[2], l[2]); bsplit(v0.w, h[3], m[3], l[3]);
            bsplit(v1.x, h[4], m[4], l[4]); bsplit(v1.y, h[5], m[5], l[5]);
            bsplit(v1.z, h[6], m[6], l[6]); bsplit(v1.w, h[7], m[7], l[7]);
            uint32_t soff = abase + (((uint32_t)(kl * 2)) ^ aswz);
            *(uint4*)(smg + GS_AH + soff) =
                make_uint4(hpack(h[0],h[1]), hpack(h[2],h[3]),
                           hpack(h[4],h[5]), hpack(h[6],h[7]));
            *(uint4*)(smg + GS_AM + soff) =
                make_uint4(hpack(m[0],m[1]), hpack(m[2],m[3]),
                           hpack(m[4],m[5]), hpack(m[6],m[7]));
            *(uint4*)(smg + GS_AL + soff) =
                make_uint4(hpack(l[0],l[1]), hpack(l[2],l[3]),
                           hpack(l[4],l[5]), hpack(l[6],l[7]));
        }
        // ---- load pre-split B tiles: 3 x (128 n x 64 k) bf16 ----
        #pragma unroll
        for (int c = tid; c < 1024; c += 256) {
            int n  = c >> 3;
            int kc = c & 7;
            int src = kt * (128 * KT) + n * KT + kc * 8;
            uint32_t dst = (uint32_t)(n * 128)
                         + (((uint32_t)(kc * 16)) ^ ((uint32_t)((n & 7) << 4)));
            *(uint4*)(smg + GS_BH + dst) = *(const uint4*)(g_Bh + src);
            *(uint4*)(smg + GS_BM + dst) = *(const uint4*)(g_Bm + src);
            *(uint4*)(smg + GS_BL + dst) = *(const uint4*)(g_Bl + src);
        }
        __syncthreads();

        // ---- compute: 4 k16 steps x 6 products x 16 mma ----
        #pragma unroll
        for (int ks = 0; ks < 4; ks++) {
            const int kb = ks * 16;
            uint32_t ah[4][4], am[4][4], bh[4][2], bm[4][2];

            #pragma unroll
            for (int mt = 0; mt < 4; mt++) {
                uint32_t row = (uint32_t)(mw * 64 + mt * 16 + ra);
                uint32_t off = row * 128 + (((uint32_t)((kb + ka) * 2)) ^ lswz);
                ldsm4(ah[mt], sbase + GS_AH + off);
                ldsm4(am[mt], sbase + GS_AM + off);
            }
            #pragma unroll
            for (int g = 0; g < 2; g++) {
                uint32_t row = (uint32_t)(nw * 32 + g * 16 + rb);
                uint32_t off = row * 128 + (((uint32_t)((kb + kbl) * 2)) ^ lswz);
                uint32_t r4[4];
                ldsm4(r4, sbase + GS_BH + off);
                bh[g*2][0] = r4[0]; bh[g*2][1] = r4[1];
                bh[g*2+1][0] = r4[2]; bh[g*2+1][1] = r4[3];
                ldsm4(r4, sbase + GS_BM + off);
                bm[g*2][0] = r4[0]; bm[g*2][1] = r4[1];
                bm[g*2+1][0] = r4[2]; bm[g*2+1][1] = r4[3];
            }
            // mm, hm
            #pragma unroll
            for (int mt = 0; mt < 4; mt++)
                #pragma unroll
                for (int nt = 0; nt < 4; nt++) {
                    mma_bf16(acc[mt][nt], am[mt], bm[nt]);
                    mma_bf16(acc[mt][nt], ah[mt], bm[nt]);
                }
            // reload bm <- bl ; mh
            #pragma unroll
            for (int g = 0; g < 2; g++) {
                uint32_t row = (uint32_t)(nw * 32 + g * 16 + rb);
                uint32_t off = row * 128 + (((uint32_t)((kb + kbl) * 2)) ^ lswz);
                uint32_t r4[4];
                ldsm4(r4, sbase + GS_BL + off);
                bm[g*2][0] = r4[0]; bm[g*2][1] = r4[1];
                bm[g*2+1][0] = r4[2]; bm[g*2+1][1] = r4[3];
            }
            #pragma unroll
            for (int mt = 0; mt < 4; mt++)
                #pragma unroll
                for (int nt = 0; nt < 4; nt++)
                    mma_bf16(acc[mt][nt], am[mt], bh[nt]);   // mh
            // reload am <- al ; hl, lh, hh
            #pragma unroll
            for (int mt = 0; mt < 4; mt++) {
                uint32_t row = (uint32_t)(mw * 64 + mt * 16 + ra);
                uint32_t off = row * 128 + (((uint32_t)((kb + ka) * 2)) ^ lswz);
                ldsm4(am[mt], sbase + GS_AL + off);
            }
            #pragma unroll
            for (int mt = 0; mt < 4; mt++)
                #pragma unroll
                for (int nt = 0; nt < 4; nt++) {
                    mma_bf16(acc[mt][nt], ah[mt], bm[nt]);   // hl
                    mma_bf16(acc[mt][nt], am[mt], bh[nt]);   // lh
                    mma_bf16(acc[mt][nt], ah[mt], bh[nt]);   // hh
                }
        }
        __syncthreads();
    }

    // ---- epilogue: scatter to g_h1[t][b][h] with bias ----
    const float* sb1 = (const float*)(smg + GS_BIAS);
    const int r_lo = lane >> 2;
    const int c_lo = (lane & 3) * 2;
    #pragma unroll
    for (int mt = 0; mt < 4; mt++) {
        #pragma unroll
        for (int half = 0; half < 2; half++) {
            int mrow = m0 + mw * 64 + mt * 16 + r_lo + half * 8;
            int b = mrow / Tsz;
            int t = mrow - b * Tsz;
            float* orow = g_h1 + (size_t)t * (Bsz * Hd) + b * Hd;
            #pragma unroll
            for (int nt = 0; nt < 4; nt++) {
                int c = nw * 32 + nt * 8 + c_lo;
                float2 v;
                v.x = acc[mt][nt][half * 2 + 0] + sb1[c];
                v.y = acc[mt][nt][half * 2 + 1] + sb1[c + 1];
                *(float2*)(orow + c) = v;
            }
        }
    }
}

// ---------------------------------------------------------------------------
// Kernel 2: persistent recurrent LIF loop (unchanged from R2, 137us)
// ---------------------------------------------------------------------------
#define SM_W0   0
#define SM_W1   16384
#define SM_W2   32768
#define SM_W3   49152
#define SM_RCB1 51712
#define SM_B2C  51840
#define SM_WM1  51968
#define SM_WM2  51976
#define SM_FLOATS 51984
#define SM_BYTES  (SM_FLOATS * 4)

__global__ void __launch_bounds__(256, 1) rec_kernel(
    const float* __restrict__ rcW1, const float* __restrict__ rcb1,
    const float* __restrict__ W2,   const float* __restrict__ b2,
    const float* __restrict__ rcW2, const float* __restrict__ rcb2,
    const float* __restrict__ W3,   const float* __restrict__ b3,
    float* __restrict__ out)
{
    extern __shared__ float sm[];
    float* sW0   = sm + SM_W0;
    float* sW1   = sm + SM_W1;
    float* sW2   = sm + SM_W2;
    float* sW3   = sm + SM_W3;
    float* srcb1 = sm + SM_RCB1;
    float* sb2c  = sm + SM_B2C;
    unsigned* swm1 = (unsigned*)(sm + SM_WM1);
    unsigned* swm2 = (unsigned*)(sm + SM_WM2);

    const int tid = threadIdx.x;

    {
        const float4* a = (const float4*)rcW1;
        const float4* c = (const float4*)W2;
        const float4* d = (const float4*)rcW2;
        float4* o0 = (float4*)sW0; float4* o1 = (float4*)sW1; float4* o2 = (float4*)sW2;
        for (int i = tid; i < (Hd * Hd) / 4; i += 256) {
            o0[i] = a[i]; o1[i] = c[i]; o2[i] = d[i];
        }
    }
    for (int i = tid; i < Hd * DOUT; i += 256) sW3[i] = W3[i];
    if (tid < Hd) {
        srcb1[tid] = rcb1[tid];
        sb2c[tid]  = b2[tid] + rcb2[tid];
    }
    __syncthreads();

    const int hb   = tid >> 7;
    const int j    = tid & 127;
    const int b    = blockIdx.x * 2 + hb;
    const int lane = tid & 31;
    const int w    = (tid >> 5) & 3;
    const int barid = 1 + hb;

    unsigned* wm1 = swm1 + hb * 4;
    unsigned* wm2 = swm2 + hb * 4;

    float v1 = 0.f, v2 = 0.f, acc = 0.f;
    unsigned m1[4] = {0u, 0u, 0u, 0u};
    unsigned m2[4] = {0u, 0u, 0u, 0u};

    const float* h1p = g_h1 + b * Hd + j;
    float h1v = h1p[0];

    for (int t = 0; t < Tsz; t++) {
        float h1n = (t + 1 < Tsz) ? h1p[(size_t)(t + 1) * (Bsz * Hd)] : 0.f;

        float u = h1v + srcb1[j];
        #pragma unroll
        for (int q = 0; q < 4; q++) {
            unsigned mm = m1[q];
            const float* wp = sW0 + q * 32 * Hd + j;
            while (mm) {
                int i = __ffs(mm) - 1; mm &= mm - 1u;
                u += wp[i * Hd];
            }
        }
        v1 += (u - v1) * 0.5f;
        bool s1 = (v1 >= 1.0f);
        if (s1) v1 = 0.f;

        unsigned bal = __ballot_sync(0xffffffffu, s1);
        if (lane == 0) wm1[w] = bal;
        asm volatile("bar.sync %0, 128;" :: "r"(barid) : "memory");
        m1[0] = wm1[0]; m1[1] = wm1[1]; m1[2] = wm1[2]; m1[3] = wm1[3];

        float u2 = sb2c[j];
        #pragma unroll
        for (int q = 0; q < 4; q++) {
            unsigned mm = m1[q];
            const float* wp = sW1 + q * 32 * Hd + j;
            while (mm) {
                int i = __ffs(mm) - 1; mm &= mm - 1u;
                u2 += wp[i * Hd];
            }
        }
        #pragma unroll
        for (int q = 0; q < 4; q++) {
            unsigned mm = m2[q];
            const float* wp = sW2 + q * 32 * Hd + j;
            while (mm) {
                int i = __ffs(mm) - 1; mm &= mm - 1u;
                u2 += wp[i * Hd];
            }
        }
        v2 += (u2 - v2) * 0.5f;
        bool s2 = (v2 >= 1.0f);
        if (s2) v2 = 0.f;

        bal = __ballot_sync(0xffffffffu, s2);
        if (lane == 0) wm2[w] = bal;
        asm volatile("bar.sync %0, 128;" :: "r"(barid) : "memory");
        m2[0] = wm2[0]; m2[1] = wm2[1]; m2[2] = wm2[2]; m2[3] = wm2[3];

        if (j < DOUT) {
            float a = 0.f;
            #pragma unroll
            for (int q = 0; q < 4; q++) {
                unsigned mm = m2[q];
                const float* wp = sW3 + q * 32 * DOUT + j;
                while (mm) {
                    int i = __ffs(mm) - 1; mm &= mm - 1u;
                    a += wp[i * DOUT];
                }
            }
            acc += a;
        }
        h1v = h1n;
    }

    if (j < DOUT)
        out[b * DOUT + j] = acc + (float)Tsz * b3[j];
}

// ---------------------------------------------------------------------------
// Launch
// ---------------------------------------------------------------------------
extern "C" void kernel_launch(void* const* d_in, const int* in_sizes, int n_in,
                              void* d_out, int out_size)
{
    const float* x    = (const float*)d_in[0];
    const float* W1   = (const float*)d_in[1];
    const float* b1   = (const float*)d_in[2];
    const float* rcW1 = (const float*)d_in[3];
    const float* rcb1 = (const float*)d_in[4];
    const float* W2   = (const float*)d_in[5];
    const float* b2   = (const float*)d_in[6];
    const float* rcW2 = (const float*)d_in[7];
    const float* rcb2 = (const float*)d_in[8];
    const float* W3   = (const float*)d_in[9];
    const float* b3   = (const float*)d_in[10];
    float* out = (float*)d_out;

    cudaFuncSetAttribute(gemm1_kernel,
                         cudaFuncAttributeMaxDynamicSharedMemorySize, GS_BYTES);
    cudaFuncSetAttribute(rec_kernel,
                         cudaFuncAttributeMaxDynamicSharedMemorySize, SM_BYTES);

    // 0) split W1 into bf16 h/m/l tiles
    prep_kernel<<<(NKT * 128 * KT + 255) / 256, 256>>>(W1);

    // 1) h1_all = x @ W1 + b1 (bf16x3 six-product HMMA, fp32-accurate)
    gemm1_kernel<<<(Bsz * Tsz) / 128, 256, GS_BYTES>>>(x, b1);

    // 2) recurrent LIF loop
    rec_kernel<<<Bsz / 2, 256, SM_BYTES>>>(rcW1, rcb1, W2, b2,
                                           rcW2, rcb2, W3, b3, out);
}